// round 2
// baseline (speedup 1.0000x reference)
#include <cuda_runtime.h>
#include <math.h>

#define NTOK 25088          // 8*56*56
#define CDIM 256

// ---------------- scratch (static device allocations; no cudaMalloc) ----------------
__device__ float g_img[(size_t)NTOK * 256];   // LN1 output, reused for LN2 output
__device__ float g_qkv[(size_t)NTOK * 768];
__device__ float g_att[(size_t)NTOK * 256];
__device__ float g_x1 [(size_t)NTOK * 256];   // x + attn-proj (first residual)
__device__ float g_fc1[(size_t)NTOK * 1024];

// ---------------- LayerNorm: one warp per token (C=256 -> 8 floats/lane) ----------------
__global__ void ln_kernel(const float* __restrict__ x, const float* __restrict__ g,
                          const float* __restrict__ b, float* __restrict__ out) {
    int warp = threadIdx.x >> 5, lane = threadIdx.x & 31;
    int t = blockIdx.x * 8 + warp;
    const float* xp = x + (size_t)t * 256;
    float v[8]; float s = 0.f, s2 = 0.f;
#pragma unroll
    for (int i = 0; i < 8; i++) { v[i] = xp[lane + 32 * i]; s += v[i]; s2 += v[i] * v[i]; }
#pragma unroll
    for (int o = 16; o; o >>= 1) {
        s  += __shfl_xor_sync(0xffffffffu, s,  o);
        s2 += __shfl_xor_sync(0xffffffffu, s2, o);
    }
    float mean = s * (1.f / 256.f);
    float var  = s2 * (1.f / 256.f) - mean * mean;
    float rstd = rsqrtf(var + 1e-5f);
    float* op = out + (size_t)t * 256;
#pragma unroll
    for (int i = 0; i < 8; i++) {
        int c = lane + 32 * i;
        op[c] = (v[i] - mean) * rstd * g[c] + b[c];
    }
}

// ---------------- generic SGEMM: C = A[M,K] @ B[K,N] (+bias)(GELU)(+res) ----------------
__device__ __forceinline__ float gelu_f(float x) {
    return 0.5f * x * (1.f + erff(x * 0.70710678118654752f));
}

template<bool BIAS, bool RES, bool GELU_>
__global__ void sgemm_kernel(const float* __restrict__ A, const float* __restrict__ B,
                             float* __restrict__ C, int M, int N, int K,
                             const float* __restrict__ bias, const float* __restrict__ res) {
    __shared__ float As[16][68];   // As[k][m] (transposed A tile)
    __shared__ float Bs[16][68];   // Bs[k][n]
    const int tid = threadIdx.x;
    const int tx = tid & 15, ty = tid >> 4;
    const int m0 = blockIdx.y * 64, n0 = blockIdx.x * 64;
    const int arow = tid >> 2,  akq  = (tid & 3)  * 4;
    const int brow = tid >> 4,  bcol = (tid & 15) * 4;

    float acc[4][4] = {};
    for (int k0 = 0; k0 < K; k0 += 16) {
        float4 av = *(const float4*)&A[(size_t)(m0 + arow) * K + k0 + akq];
        As[akq + 0][arow] = av.x; As[akq + 1][arow] = av.y;
        As[akq + 2][arow] = av.z; As[akq + 3][arow] = av.w;
        *(float4*)&Bs[brow][bcol] = *(const float4*)&B[(size_t)(k0 + brow) * N + n0 + bcol];
        __syncthreads();
#pragma unroll
        for (int k = 0; k < 16; k++) {
            float4 a = *(const float4*)&As[k][ty * 4];
            float4 b = *(const float4*)&Bs[k][tx * 4];
            float aa[4] = { a.x, a.y, a.z, a.w };
            float bb[4] = { b.x, b.y, b.z, b.w };
#pragma unroll
            for (int i = 0; i < 4; i++)
#pragma unroll
                for (int j = 0; j < 4; j++)
                    acc[i][j] = fmaf(aa[i], bb[j], acc[i][j]);
        }
        __syncthreads();
    }

#pragma unroll
    for (int i = 0; i < 4; i++) {
        int row = m0 + ty * 4 + i;
        int col = n0 + tx * 4;
        float4 v = make_float4(acc[i][0], acc[i][1], acc[i][2], acc[i][3]);
        if (BIAS) {
            float4 bb = *(const float4*)&bias[col];
            v.x += bb.x; v.y += bb.y; v.z += bb.z; v.w += bb.w;
        }
        if (GELU_) { v.x = gelu_f(v.x); v.y = gelu_f(v.y); v.z = gelu_f(v.z); v.w = gelu_f(v.w); }
        if (RES) {
            float4 r = *(const float4*)&res[(size_t)row * N + col];
            v.x += r.x; v.y += r.y; v.z += r.z; v.w += r.w;
        }
        *(float4*)&C[(size_t)row * N + col] = v;
    }
}

// ---------------- fused cross-window attention + LePE ----------------
// One CTA per (window, head). L=392 tokens/window, hd=32.
// smem: Kt[32][400] + V[392][32] + q-stage[8][32]f4 + scores[8][392]f4 = 152 KB
// BR=0: H_sp=56,W_sp=7 (vertical stripes); BR=1: H_sp=7,W_sp=56 (horizontal)
#define ATTN_SMEM 155648

template<int BR>
__global__ void attn_kernel(const float* __restrict__ qkv,
                            const float* __restrict__ lw, const float* __restrict__ lb,
                            float* __restrict__ att) {
    constexpr int H_sp = BR ? 7 : 56;
    constexpr int W_sp = BR ? 56 : 7;
    extern __shared__ float smem[];
    float*  Kt  = smem;                           // [32][400]
    float*  Vs  = smem + 32 * 400;                // [392][32]
    float4* qs4 = (float4*)(Vs + 392 * 32);       // [8 warps][32]
    float4* sc  = qs4 + 8 * 32;                   // [8 warps][392]

    const int win  = blockIdx.x >> 2;
    const int head = blockIdx.x & 3;
    const int cbase = BR * 128 + head * 32;
    const int tid = threadIdx.x;
    const int lane = tid & 31, wi = tid >> 5;
    const int bimg = win >> 3, wsub = win & 7;

    // stage K (transposed) and V
    for (int idx = tid; idx < 392 * 32; idx += 256) {
        int l = idx >> 5, d = idx & 31;
        int i = l / W_sp, j = l - i * W_sp;
        int h = BR ? (wsub * 7 + i) : i;
        int w = BR ? j : (wsub * 7 + j);
        size_t t = (size_t)bimg * 3136 + h * 56 + w;
        const float* base = qkv + t * 768 + cbase + d;
        Kt[d * 400 + l] = base[256];
        Vs[idx]         = base[512];
    }
    // LePE depthwise 3x3 weights for this lane's channel (loop-invariant)
    const int cl = head * 32 + lane;
    float wreg[9];
#pragma unroll
    for (int k = 0; k < 9; k++) wreg[k] = lw[cl * 9 + k];
    const float breg = lb[cl];
    __syncthreads();

    const float scale = 0.17677669529663689f;  // 32^-0.5

    for (int grp = wi; grp < 98; grp += 8) {    // 4 queries per warp-iteration
        const int l0 = grp * 4;
        // stage q (scaled) as [d][query] float4 for broadcast reads
        {
            float qq[4];
#pragma unroll
            for (int qi = 0; qi < 4; qi++) {
                int l = l0 + qi;
                int i = l / W_sp, j = l - i * W_sp;
                int h = BR ? (wsub * 7 + i) : i;
                int w = BR ? j : (wsub * 7 + j);
                size_t t = (size_t)bimg * 3136 + h * 56 + w;
                qq[qi] = qkv[t * 768 + cbase + lane] * scale;
            }
            qs4[wi * 32 + lane] = make_float4(qq[0], qq[1], qq[2], qq[3]);
        }
        __syncwarp();

        // scores: lane owns keys m = lane + 32*mt
        float mx0 = -1e30f, mx1 = -1e30f, mx2 = -1e30f, mx3 = -1e30f;
        for (int mt = 0; mt < 13; mt++) {
            int m = mt * 32 + lane;
            if (m < 392) {
                float a0 = 0.f, a1 = 0.f, a2 = 0.f, a3 = 0.f;
#pragma unroll
                for (int d = 0; d < 32; d++) {
                    float kv = Kt[d * 400 + m];
                    float4 q = qs4[wi * 32 + d];
                    a0 = fmaf(kv, q.x, a0); a1 = fmaf(kv, q.y, a1);
                    a2 = fmaf(kv, q.z, a2); a3 = fmaf(kv, q.w, a3);
                }
                sc[wi * 392 + m] = make_float4(a0, a1, a2, a3);
                mx0 = fmaxf(mx0, a0); mx1 = fmaxf(mx1, a1);
                mx2 = fmaxf(mx2, a2); mx3 = fmaxf(mx3, a3);
            }
        }
#pragma unroll
        for (int o = 16; o; o >>= 1) {
            mx0 = fmaxf(mx0, __shfl_xor_sync(0xffffffffu, mx0, o));
            mx1 = fmaxf(mx1, __shfl_xor_sync(0xffffffffu, mx1, o));
            mx2 = fmaxf(mx2, __shfl_xor_sync(0xffffffffu, mx2, o));
            mx3 = fmaxf(mx3, __shfl_xor_sync(0xffffffffu, mx3, o));
        }
        // exp + sum
        float s0 = 0.f, s1 = 0.f, s2 = 0.f, s3 = 0.f;
        for (int mt = 0; mt < 13; mt++) {
            int m = mt * 32 + lane;
            if (m < 392) {
                float4 e = sc[wi * 392 + m];
                e.x = __expf(e.x - mx0); e.y = __expf(e.y - mx1);
                e.z = __expf(e.z - mx2); e.w = __expf(e.w - mx3);
                sc[wi * 392 + m] = e;
                s0 += e.x; s1 += e.y; s2 += e.z; s3 += e.w;
            }
        }
#pragma unroll
        for (int o = 16; o; o >>= 1) {
            s0 += __shfl_xor_sync(0xffffffffu, s0, o);
            s1 += __shfl_xor_sync(0xffffffffu, s1, o);
            s2 += __shfl_xor_sync(0xffffffffu, s2, o);
            s3 += __shfl_xor_sync(0xffffffffu, s3, o);
        }
        const float i0 = 1.f / s0, i1 = 1.f / s1, i2 = 1.f / s2, i3 = 1.f / s3;
        __syncwarp();

        // AV: lane owns output channel d = lane
        float o0 = 0.f, o1 = 0.f, o2 = 0.f, o3 = 0.f;
#pragma unroll 4
        for (int m = 0; m < 392; m++) {
            float v  = Vs[m * 32 + lane];
            float4 p = sc[wi * 392 + m];
            o0 = fmaf(p.x, v, o0); o1 = fmaf(p.y, v, o1);
            o2 = fmaf(p.z, v, o2); o3 = fmaf(p.w, v, o3);
        }
        float outs[4] = { o0 * i0, o1 * i1, o2 * i2, o3 * i3 };

        // LePE (depthwise 3x3 on V window, zero-pad at window edges) + store
#pragma unroll
        for (int qi = 0; qi < 4; qi++) {
            int l = l0 + qi;
            int i = l / W_sp, j = l - i * W_sp;
            float acc = breg;
#pragma unroll
            for (int ki = 0; ki < 3; ki++) {
                int ii = i + ki - 1;
                if (ii >= 0 && ii < H_sp) {
#pragma unroll
                    for (int kj = 0; kj < 3; kj++) {
                        int jj = j + kj - 1;
                        if (jj >= 0 && jj < W_sp)
                            acc = fmaf(wreg[ki * 3 + kj], Vs[(ii * W_sp + jj) * 32 + lane], acc);
                    }
                }
            }
            int h = BR ? (wsub * 7 + i) : i;
            int w = BR ? j : (wsub * 7 + j);
            size_t t = (size_t)bimg * 3136 + h * 56 + w;
            att[t * 256 + cbase + lane] = outs[qi] + acc;
        }
        __syncwarp();   // protect qs4/sc reuse in next iteration
    }
}

// ---------------- orchestration ----------------
extern "C" void kernel_launch(void* const* d_in, const int* in_sizes, int n_in,
                              void* d_out, int out_size) {
    const float* x       = (const float*)d_in[0];
    const float* gamma1  = (const float*)d_in[1];
    const float* beta1   = (const float*)d_in[2];
    const float* w_qkv   = (const float*)d_in[3];
    const float* lepe_w0 = (const float*)d_in[4];
    const float* lepe_b0 = (const float*)d_in[5];
    const float* lepe_w1 = (const float*)d_in[6];
    const float* lepe_b1 = (const float*)d_in[7];
    const float* w_proj  = (const float*)d_in[8];
    const float* b_proj  = (const float*)d_in[9];
    const float* gamma2  = (const float*)d_in[10];
    const float* beta2   = (const float*)d_in[11];
    const float* w_fc1   = (const float*)d_in[12];
    const float* b_fc1   = (const float*)d_in[13];
    const float* w_fc2   = (const float*)d_in[14];
    const float* b_fc2   = (const float*)d_in[15];
    float* out = (float*)d_out;

    float *img, *qkvb, *attb, *x1b, *fc1b;
    cudaGetSymbolAddress((void**)&img,  g_img);
    cudaGetSymbolAddress((void**)&qkvb, g_qkv);
    cudaGetSymbolAddress((void**)&attb, g_att);
    cudaGetSymbolAddress((void**)&x1b,  g_x1);
    cudaGetSymbolAddress((void**)&fc1b, g_fc1);

    cudaFuncSetAttribute(attn_kernel<0>, cudaFuncAttributeMaxDynamicSharedMemorySize, ATTN_SMEM);
    cudaFuncSetAttribute(attn_kernel<1>, cudaFuncAttributeMaxDynamicSharedMemorySize, ATTN_SMEM);

    // 1) LN1
    ln_kernel<<<NTOK / 8, 256>>>(x, gamma1, beta1, img);
    // 2) qkv = img @ w_qkv   [25088,768]
    sgemm_kernel<false, false, false><<<dim3(768 / 64, NTOK / 64), 256>>>(
        img, w_qkv, qkvb, NTOK, 768, 256, nullptr, nullptr);
    // 3) both attention branches (64 windows x 4 heads each)
    attn_kernel<0><<<256, 256, ATTN_SMEM>>>(qkvb, lepe_w0, lepe_b0, attb);
    attn_kernel<1><<<256, 256, ATTN_SMEM>>>(qkvb, lepe_w1, lepe_b1, attb);
    // 4) x1 = x + att @ w_proj + b_proj
    sgemm_kernel<true, true, false><<<dim3(256 / 64, NTOK / 64), 256>>>(
        attb, w_proj, x1b, NTOK, 256, 256, b_proj, x);
    // 5) LN2
    ln_kernel<<<NTOK / 8, 256>>>(x1b, gamma2, beta2, img);
    // 6) fc1 + GELU(exact)
    sgemm_kernel<true, false, true><<<dim3(1024 / 64, NTOK / 64), 256>>>(
        img, w_fc1, fc1b, NTOK, 1024, 256, b_fc1, nullptr);
    // 7) out = x1 + fc1g @ w_fc2 + b_fc2
    sgemm_kernel<true, true, false><<<dim3(256 / 64, NTOK / 64), 256>>>(
        fc1b, w_fc2, out, NTOK, 256, 1024, b_fc2, x1b);
}

// round 3
// speedup vs baseline: 1.5113x; 1.5113x over previous
#include <cuda_runtime.h>
#include <cuda_fp16.h>
#include <math.h>
#include <stdint.h>

#define NTOK 25088          // 8*56*56
#define CDIM 256

// ---------------- scratch (static device allocations; no cudaMalloc) ----------------
__device__ float g_img[(size_t)NTOK * 256];   // LN1 output, reused for LN2 output
__device__ float g_qkv[(size_t)NTOK * 768];
__device__ float g_att[(size_t)NTOK * 256];
__device__ float g_x1 [(size_t)NTOK * 256];   // x + attn-proj (first residual)
__device__ float g_fc1[(size_t)NTOK * 1024];

// ---------------- LayerNorm: one warp per token (C=256 -> 8 floats/lane) ----------------
__global__ void ln_kernel(const float* __restrict__ x, const float* __restrict__ g,
                          const float* __restrict__ b, float* __restrict__ out) {
    int warp = threadIdx.x >> 5, lane = threadIdx.x & 31;
    int t = blockIdx.x * 8 + warp;
    const float* xp = x + (size_t)t * 256;
    float v[8]; float s = 0.f, s2 = 0.f;
#pragma unroll
    for (int i = 0; i < 8; i++) { v[i] = xp[lane + 32 * i]; s += v[i]; s2 += v[i] * v[i]; }
#pragma unroll
    for (int o = 16; o; o >>= 1) {
        s  += __shfl_xor_sync(0xffffffffu, s,  o);
        s2 += __shfl_xor_sync(0xffffffffu, s2, o);
    }
    float mean = s * (1.f / 256.f);
    float var  = s2 * (1.f / 256.f) - mean * mean;
    float rstd = rsqrtf(var + 1e-5f);
    float* op = out + (size_t)t * 256;
#pragma unroll
    for (int i = 0; i < 8; i++) {
        int c = lane + 32 * i;
        op[c] = (v[i] - mean) * rstd * g[c] + b[c];
    }
}

// ---------------- tf32 tensor-core GEMM: C = A[M,K] @ B[K,N] (+bias)(GELU)(+res) ----------------
__device__ __forceinline__ float gelu_f(float x) {
    return 0.5f * x * (1.f + erff(x * 0.70710678118654752f));
}
__device__ __forceinline__ uint32_t f2tf(float f) {
    uint32_t u; asm("cvt.rna.tf32.f32 %0, %1;" : "=r"(u) : "f"(f)); return u;
}

// BM=128, BN=64, BK=32; 256 threads = 8 warps (4 along M x 2 along N), warp tile 32x32.
// mma.sync.aligned.m16n8k8.row.col.f32.tf32.tf32.f32 -> per warp 2(m) x 4(n) tiles / k-step.
template<bool BIAS, bool RES, bool GELU_>
__global__ void __launch_bounds__(256) mma_gemm(const float* __restrict__ A,
                                                const float* __restrict__ B,
                                                float* __restrict__ C, int M, int N, int K,
                                                const float* __restrict__ bias,
                                                const float* __restrict__ res) {
    __shared__ uint32_t As[32][136];   // [k][m], pad 8 -> conflict-free fragment loads
    __shared__ uint32_t Bs[32][72];    // [k][n], pad 8

    const int tid  = threadIdx.x, lane = tid & 31, warp = tid >> 5;
    const int wm   = (warp & 3) * 32, wn = (warp >> 2) * 32;
    const int gid  = lane >> 2, tig = lane & 3;
    const int m0   = blockIdx.y * 128, n0 = blockIdx.x * 64;
    const int ar   = tid >> 3, ac = (tid & 7) * 4;
    const int br   = tid >> 4, bc = (tid & 15) * 4;

    float acc[2][4][4];
#pragma unroll
    for (int i = 0; i < 2; i++)
#pragma unroll
        for (int j = 0; j < 4; j++)
#pragma unroll
            for (int l = 0; l < 4; l++) acc[i][j][l] = 0.f;

    for (int k0 = 0; k0 < K; k0 += 32) {
#pragma unroll
        for (int i = 0; i < 4; i++) {
            float4 v = *(const float4*)&A[(size_t)(m0 + ar + 32 * i) * K + k0 + ac];
            int mcol = ar + 32 * i;
            As[ac + 0][mcol] = f2tf(v.x); As[ac + 1][mcol] = f2tf(v.y);
            As[ac + 2][mcol] = f2tf(v.z); As[ac + 3][mcol] = f2tf(v.w);
        }
#pragma unroll
        for (int i = 0; i < 2; i++) {
            float4 v = *(const float4*)&B[(size_t)(k0 + br + 16 * i) * N + n0 + bc];
            uint4 u = make_uint4(f2tf(v.x), f2tf(v.y), f2tf(v.z), f2tf(v.w));
            *(uint4*)&Bs[br + 16 * i][bc] = u;
        }
        __syncthreads();

#pragma unroll
        for (int ks = 0; ks < 4; ks++) {
            const int k1 = ks * 8 + tig, k2 = k1 + 4;
            uint32_t a[2][4], b[4][2];
#pragma unroll
            for (int mt = 0; mt < 2; mt++) {
                int rb = wm + mt * 16 + gid;
                a[mt][0] = As[k1][rb];     a[mt][1] = As[k1][rb + 8];
                a[mt][2] = As[k2][rb];     a[mt][3] = As[k2][rb + 8];
            }
#pragma unroll
            for (int nt = 0; nt < 4; nt++) {
                int nb = wn + nt * 8 + gid;
                b[nt][0] = Bs[k1][nb];     b[nt][1] = Bs[k2][nb];
            }
#pragma unroll
            for (int mt = 0; mt < 2; mt++)
#pragma unroll
                for (int nt = 0; nt < 4; nt++) {
                    asm volatile(
                        "mma.sync.aligned.m16n8k8.row.col.f32.tf32.tf32.f32 "
                        "{%0,%1,%2,%3},{%4,%5,%6,%7},{%8,%9},{%0,%1,%2,%3};"
                        : "+f"(acc[mt][nt][0]), "+f"(acc[mt][nt][1]),
                          "+f"(acc[mt][nt][2]), "+f"(acc[mt][nt][3])
                        : "r"(a[mt][0]), "r"(a[mt][1]), "r"(a[mt][2]), "r"(a[mt][3]),
                          "r"(b[nt][0]), "r"(b[nt][1]));
                }
        }
        __syncthreads();
    }

    // epilogue: c0,c1 at (row, col..col+1); c2,c3 at (row+8, ...)
#pragma unroll
    for (int mt = 0; mt < 2; mt++)
#pragma unroll
        for (int nt = 0; nt < 4; nt++) {
            int row = m0 + wm + mt * 16 + gid;
            int col = n0 + wn + nt * 8 + 2 * tig;
            float2 v0 = make_float2(acc[mt][nt][0], acc[mt][nt][1]);
            float2 v1 = make_float2(acc[mt][nt][2], acc[mt][nt][3]);
            if (BIAS) {
                float2 bb = *(const float2*)&bias[col];
                v0.x += bb.x; v0.y += bb.y; v1.x += bb.x; v1.y += bb.y;
            }
            if (GELU_) {
                v0.x = gelu_f(v0.x); v0.y = gelu_f(v0.y);
                v1.x = gelu_f(v1.x); v1.y = gelu_f(v1.y);
            }
            if (RES) {
                float2 r0 = *(const float2*)&res[(size_t)row * N + col];
                float2 r1 = *(const float2*)&res[(size_t)(row + 8) * N + col];
                v0.x += r0.x; v0.y += r0.y; v1.x += r1.x; v1.y += r1.y;
            }
            *(float2*)&C[(size_t)row * N + col]       = v0;
            *(float2*)&C[(size_t)(row + 8) * N + col] = v1;
        }
}

// ---------------- fused cross-window attention + LePE ----------------
// One CTA per (window, head). L=392 tokens/window, hd=32.
// K/V tiles stored fp16 -> smem = 104960B -> 2 CTAs/SM (16 warps), grid fits one wave.
#define ATTN_SMEM 104960

template<int BR>
__global__ void __launch_bounds__(256, 2) attn_kernel(const float* __restrict__ qkv,
                            const float* __restrict__ lw, const float* __restrict__ lb,
                            float* __restrict__ att) {
    constexpr int H_sp = BR ? 7 : 56;
    constexpr int W_sp = BR ? 56 : 7;
    extern __shared__ char smem_raw[];
    __half* Kt  = (__half*)smem_raw;                    // [32][400]  25600B
    __half* Vs  = Kt + 32 * 400;                        // [392][32]  25088B
    float4* qs4 = (float4*)(smem_raw + 50688);          // [8 warps][32]  4096B
    float4* sc  = qs4 + 8 * 32;                         // [8 warps][392] 50176B

    const int win  = blockIdx.x >> 2;
    const int head = blockIdx.x & 3;
    const int cbase = BR * 128 + head * 32;
    const int tid = threadIdx.x;
    const int lane = tid & 31, wi = tid >> 5;
    const int bimg = win >> 3, wsub = win & 7;

    // stage K (transposed, fp16) and V (fp16)
    for (int idx = tid; idx < 392 * 32; idx += 256) {
        int l = idx >> 5, d = idx & 31;
        int i = l / W_sp, j = l - i * W_sp;
        int h = BR ? (wsub * 7 + i) : i;
        int w = BR ? j : (wsub * 7 + j);
        size_t t = (size_t)bimg * 3136 + h * 56 + w;
        const float* base = qkv + t * 768 + cbase + d;
        Kt[d * 400 + l] = __float2half(base[256]);
        Vs[idx]         = __float2half(base[512]);
    }
    // LePE depthwise 3x3 weights for this lane's channel (loop-invariant)
    const int cl = head * 32 + lane;
    float wreg[9];
#pragma unroll
    for (int k = 0; k < 9; k++) wreg[k] = lw[cl * 9 + k];
    const float breg = lb[cl];
    __syncthreads();

    const float scale = 0.17677669529663689f;  // 32^-0.5

    for (int grp = wi; grp < 98; grp += 8) {    // 4 queries per warp-iteration
        const int l0 = grp * 4;
        {
            float qq[4];
#pragma unroll
            for (int qi = 0; qi < 4; qi++) {
                int l = l0 + qi;
                int i = l / W_sp, j = l - i * W_sp;
                int h = BR ? (wsub * 7 + i) : i;
                int w = BR ? j : (wsub * 7 + j);
                size_t t = (size_t)bimg * 3136 + h * 56 + w;
                qq[qi] = qkv[t * 768 + cbase + lane] * scale;
            }
            qs4[wi * 32 + lane] = make_float4(qq[0], qq[1], qq[2], qq[3]);
        }
        __syncwarp();

        // scores: lane owns keys m = lane + 32*mt
        float mx0 = -1e30f, mx1 = -1e30f, mx2 = -1e30f, mx3 = -1e30f;
        for (int mt = 0; mt < 13; mt++) {
            int m = mt * 32 + lane;
            if (m < 392) {
                float a0 = 0.f, a1 = 0.f, a2 = 0.f, a3 = 0.f;
#pragma unroll
                for (int d = 0; d < 32; d++) {
                    float kv = __half2float(Kt[d * 400 + m]);
                    float4 q = qs4[wi * 32 + d];
                    a0 = fmaf(kv, q.x, a0); a1 = fmaf(kv, q.y, a1);
                    a2 = fmaf(kv, q.z, a2); a3 = fmaf(kv, q.w, a3);
                }
                sc[wi * 392 + m] = make_float4(a0, a1, a2, a3);
                mx0 = fmaxf(mx0, a0); mx1 = fmaxf(mx1, a1);
                mx2 = fmaxf(mx2, a2); mx3 = fmaxf(mx3, a3);
            }
        }
#pragma unroll
        for (int o = 16; o; o >>= 1) {
            mx0 = fmaxf(mx0, __shfl_xor_sync(0xffffffffu, mx0, o));
            mx1 = fmaxf(mx1, __shfl_xor_sync(0xffffffffu, mx1, o));
            mx2 = fmaxf(mx2, __shfl_xor_sync(0xffffffffu, mx2, o));
            mx3 = fmaxf(mx3, __shfl_xor_sync(0xffffffffu, mx3, o));
        }
        float s0 = 0.f, s1 = 0.f, s2 = 0.f, s3 = 0.f;
        for (int mt = 0; mt < 13; mt++) {
            int m = mt * 32 + lane;
            if (m < 392) {
                float4 e = sc[wi * 392 + m];
                e.x = __expf(e.x - mx0); e.y = __expf(e.y - mx1);
                e.z = __expf(e.z - mx2); e.w = __expf(e.w - mx3);
                sc[wi * 392 + m] = e;
                s0 += e.x; s1 += e.y; s2 += e.z; s3 += e.w;
            }
        }
#pragma unroll
        for (int o = 16; o; o >>= 1) {
            s0 += __shfl_xor_sync(0xffffffffu, s0, o);
            s1 += __shfl_xor_sync(0xffffffffu, s1, o);
            s2 += __shfl_xor_sync(0xffffffffu, s2, o);
            s3 += __shfl_xor_sync(0xffffffffu, s3, o);
        }
        const float i0 = 1.f / s0, i1 = 1.f / s1, i2 = 1.f / s2, i3 = 1.f / s3;
        __syncwarp();

        // AV: lane owns output channel d = lane
        float o0 = 0.f, o1 = 0.f, o2 = 0.f, o3 = 0.f;
#pragma unroll 4
        for (int m = 0; m < 392; m++) {
            float v  = __half2float(Vs[m * 32 + lane]);
            float4 p = sc[wi * 392 + m];
            o0 = fmaf(p.x, v, o0); o1 = fmaf(p.y, v, o1);
            o2 = fmaf(p.z, v, o2); o3 = fmaf(p.w, v, o3);
        }
        float outs[4] = { o0 * i0, o1 * i1, o2 * i2, o3 * i3 };

        // LePE (depthwise 3x3 on V window, zero-pad at window edges) + store
#pragma unroll
        for (int qi = 0; qi < 4; qi++) {
            int l = l0 + qi;
            int i = l / W_sp, j = l - i * W_sp;
            float acc = breg;
#pragma unroll
            for (int ki = 0; ki < 3; ki++) {
                int ii = i + ki - 1;
                if (ii >= 0 && ii < H_sp) {
#pragma unroll
                    for (int kj = 0; kj < 3; kj++) {
                        int jj = j + kj - 1;
                        if (jj >= 0 && jj < W_sp)
                            acc = fmaf(wreg[ki * 3 + kj],
                                       __half2float(Vs[(ii * W_sp + jj) * 32 + lane]), acc);
                    }
                }
            }
            int h = BR ? (wsub * 7 + i) : i;
            int w = BR ? j : (wsub * 7 + j);
            size_t t = (size_t)bimg * 3136 + h * 56 + w;
            att[t * 256 + cbase + lane] = outs[qi] + acc;
        }
        __syncwarp();   // protect qs4/sc reuse in next iteration
    }
}

// ---------------- orchestration ----------------
extern "C" void kernel_launch(void* const* d_in, const int* in_sizes, int n_in,
                              void* d_out, int out_size) {
    const float* x       = (const float*)d_in[0];
    const float* gamma1  = (const float*)d_in[1];
    const float* beta1   = (const float*)d_in[2];
    const float* w_qkv   = (const float*)d_in[3];
    const float* lepe_w0 = (const float*)d_in[4];
    const float* lepe_b0 = (const float*)d_in[5];
    const float* lepe_w1 = (const float*)d_in[6];
    const float* lepe_b1 = (const float*)d_in[7];
    const float* w_proj  = (const float*)d_in[8];
    const float* b_proj  = (const float*)d_in[9];
    const float* gamma2  = (const float*)d_in[10];
    const float* beta2   = (const float*)d_in[11];
    const float* w_fc1   = (const float*)d_in[12];
    const float* b_fc1   = (const float*)d_in[13];
    const float* w_fc2   = (const float*)d_in[14];
    const float* b_fc2   = (const float*)d_in[15];
    float* out = (float*)d_out;

    float *img, *qkvb, *attb, *x1b, *fc1b;
    cudaGetSymbolAddress((void**)&img,  g_img);
    cudaGetSymbolAddress((void**)&qkvb, g_qkv);
    cudaGetSymbolAddress((void**)&attb, g_att);
    cudaGetSymbolAddress((void**)&x1b,  g_x1);
    cudaGetSymbolAddress((void**)&fc1b, g_fc1);

    cudaFuncSetAttribute(attn_kernel<0>, cudaFuncAttributeMaxDynamicSharedMemorySize, ATTN_SMEM);
    cudaFuncSetAttribute(attn_kernel<1>, cudaFuncAttributeMaxDynamicSharedMemorySize, ATTN_SMEM);

    // 1) LN1
    ln_kernel<<<NTOK / 8, 256>>>(x, gamma1, beta1, img);
    // 2) qkv = img @ w_qkv   [25088,768]
    mma_gemm<false, false, false><<<dim3(768 / 64, NTOK / 128), 256>>>(
        img, w_qkv, qkvb, NTOK, 768, 256, nullptr, nullptr);
    // 3) both attention branches (64 windows x 4 heads each)
    attn_kernel<0><<<256, 256, ATTN_SMEM>>>(qkvb, lepe_w0, lepe_b0, attb);
    attn_kernel<1><<<256, 256, ATTN_SMEM>>>(qkvb, lepe_w1, lepe_b1, attb);
    // 4) x1 = x + att @ w_proj + b_proj
    mma_gemm<true, true, false><<<dim3(256 / 64, NTOK / 128), 256>>>(
        attb, w_proj, x1b, NTOK, 256, 256, b_proj, x);
    // 5) LN2
    ln_kernel<<<NTOK / 8, 256>>>(x1b, gamma2, beta2, img);
    // 6) fc1 + GELU(exact)
    mma_gemm<true, false, true><<<dim3(1024 / 64, NTOK / 128), 256>>>(
        img, w_fc1, fc1b, NTOK, 1024, 256, b_fc1, nullptr);
    // 7) out = x1 + fc1g @ w_fc2 + b_fc2
    mma_gemm<true, true, false><<<dim3(256 / 64, NTOK / 128), 256>>>(
        fc1b, w_fc2, out, NTOK, 256, 1024, b_fc2, x1b);
}